// round 2
// baseline (speedup 1.0000x reference)
#include <cuda_runtime.h>
#include <math.h>

#define NU 100000
#define NS 200000
#define DIMK 64
#define NH 2
#define HD 128          // NH * DIMK
#define EU (NU*9)
#define ESZ (NS*9)
#define BMAX 16384

// ---------------- scratch (static device globals; zero-init at module load) ----
__device__ float g_h_u[NU*HD];
__device__ float g_h_s[NS*HD];
__device__ float g_acc_u[NU*HD];
__device__ float g_acc_s[NS*HD];
__device__ float g_den_u[NU*NH];
__device__ float g_den_s[NS*NH];
__device__ float g_el_u[NU*NH];
__device__ float g_er_u[NU*NH];
__device__ float g_el_s[NS*NH];
__device__ float g_er_s[NS*NH];
__device__ int   g_need_u[NU];
__device__ int   g_need_s[NS];
__device__ int   g_sflag_u[NU];
__device__ int   g_sflag_s[NS];
__device__ int   g_slist_u[NU];
__device__ int   g_slist_s[NS];
__device__ int2  g_medge_u[EU];
__device__ int2  g_medge_s[ESZ];
__device__ int   g_cnt[4];   // [0]=nsrc_u [1]=nsrc_s [2]=nedge_u [3]=nedge_s
__device__ float g_x[BMAX*HD];

// ---------------- helpers ------------------------------------------------------
__device__ __forceinline__ void red4(float* p, float a, float b, float c, float d) {
    asm volatile("{ .reg .u64 q; cvta.to.global.u64 q, %0;"
                 "  red.global.add.v4.f32 [q], {%1, %2, %3, %4}; }"
                 :: "l"(p), "f"(a), "f"(b), "f"(c), "f"(d) : "memory");
}

#define FCMP(v,kk) ((kk)==0?(v).x:((kk)==1?(v).y:((kk)==2?(v).z:(v).w)))

// ---------------- k_zero: reset flags + counters -------------------------------
__global__ void k_zero() {
    int i = blockIdx.x*blockDim.x + threadIdx.x;
    int st = gridDim.x*blockDim.x;
    for (int j = i; j < NU; j += st) { g_need_u[j] = 0; g_sflag_u[j] = 0; }
    for (int j = i; j < NS; j += st) { g_need_s[j] = 0; g_sflag_s[j] = 0; }
    if (i < 4) g_cnt[i] = 0;
}

// ---------------- k_mark: mark needed dsts, zero their acc/den rows ------------
__global__ void __launch_bounds__(128) k_mark(const int* __restrict__ uidx,
                                              const int* __restrict__ sidx) {
    int b = blockIdx.x, t = threadIdx.x;
    int u = uidx[b], s = sidx[b];
    g_acc_u[u*HD + t] = 0.f;
    g_acc_s[s*HD + t] = 0.f;
    if (t < NH) { g_den_u[u*NH + t] = 0.f; g_den_s[s*NH + t] = 0.f; }
    if (t == 0) { g_need_u[u] = 1; g_need_s[s] = 1; }
}

// ---------------- k_compact: filter edges by needed dst; dedupe srcs -----------
__global__ void k_compact(const int* __restrict__ src, const int* __restrict__ dst,
                          int E, int user) {
    const int* need = user ? g_need_u  : g_need_s;
    int*  sflag     = user ? g_sflag_u : g_sflag_s;
    int*  slist     = user ? g_slist_u : g_slist_s;
    int2* medge     = user ? g_medge_u : g_medge_s;
    int*  cntS      = &g_cnt[user ? 0 : 1];
    int*  cntE      = &g_cnt[user ? 2 : 3];
    int st = gridDim.x*blockDim.x;
    for (int i = blockIdx.x*blockDim.x + threadIdx.x; i < E; i += st) {
        int d = dst[i];
        if (need[d]) {
            int s = src[i];
            int p = atomicAdd(cntE, 1);
            medge[p] = make_int2(s, d);
            if (atomicExch(&sflag[s], 1) == 0)
                slist[atomicAdd(cntS, 1)] = s;
        }
    }
}

// ---------------- k_h: h = emb@W (register-tiled), plus el/er, for flagged srcs
__global__ void __launch_bounds__(256,4) k_h(const float* __restrict__ emb,
                                             const float* __restrict__ W,
                                             const float* __restrict__ al_,
                                             const float* __restrict__ ar_,
                                             int user) {
    float* h  = user ? g_h_u  : g_h_s;
    float* el = user ? g_el_u : g_el_s;
    float* er = user ? g_er_u : g_er_s;
    const int* slist = user ? g_slist_u : g_slist_s;
    int nsrc = g_cnt[user ? 0 : 1];

    __shared__ float Ws[DIMK*HD];      // 32 KB
    __shared__ float Es[32][DIMK];     // 8 KB
    __shared__ float als[HD], ars[HD];
    __shared__ int   rows[32];

    int tile0 = blockIdx.x * 32;
    if (tile0 >= nsrc) return;
    int tid = threadIdx.x;

    for (int i = tid; i < DIMK*HD; i += 256) Ws[i] = W[i];
    if (tid < HD) { als[tid] = al_[tid]; ars[tid] = ar_[tid]; }
    if (tid < 32) rows[tid] = (tile0 + tid < nsrc) ? slist[tile0 + tid] : -1;
    __syncthreads();
    for (int idx = tid; idx < 32*DIMK; idx += 256) {
        int r = idx >> 6, k = idx & 63;
        int node = rows[r];
        Es[r][k] = (node >= 0) ? emb[node*DIMK + k] : 0.f;
    }
    __syncthreads();

    int w = tid >> 5, l = tid & 31;
    int r0 = w * 4, c0 = l * 4;
    float acc[4][4] = {};

    for (int k4 = 0; k4 < DIMK; k4 += 4) {
        float4 A0 = *(const float4*)&Es[r0+0][k4];
        float4 A1 = *(const float4*)&Es[r0+1][k4];
        float4 A2 = *(const float4*)&Es[r0+2][k4];
        float4 A3 = *(const float4*)&Es[r0+3][k4];
        #pragma unroll
        for (int kk = 0; kk < 4; kk++) {
            float4 wv = *(const float4*)&Ws[(k4+kk)*HD + c0];
            float e0 = FCMP(A0,kk), e1 = FCMP(A1,kk), e2 = FCMP(A2,kk), e3 = FCMP(A3,kk);
            acc[0][0] += e0*wv.x; acc[0][1] += e0*wv.y; acc[0][2] += e0*wv.z; acc[0][3] += e0*wv.w;
            acc[1][0] += e1*wv.x; acc[1][1] += e1*wv.y; acc[1][2] += e1*wv.z; acc[1][3] += e1*wv.w;
            acc[2][0] += e2*wv.x; acc[2][1] += e2*wv.y; acc[2][2] += e2*wv.z; acc[2][3] += e2*wv.w;
            acc[3][0] += e3*wv.x; acc[3][1] += e3*wv.y; acc[3][2] += e3*wv.z; acc[3][3] += e3*wv.w;
        }
    }

    int head = l >> 4;   // lanes 0-15 head0, 16-31 head1 (c0 = l*4)
    #pragma unroll
    for (int i = 0; i < 4; i++) {
        int node = rows[r0+i];
        if (node >= 0)
            *(float4*)&h[node*HD + c0] = make_float4(acc[i][0], acc[i][1], acc[i][2], acc[i][3]);
        float pl = acc[i][0]*als[c0] + acc[i][1]*als[c0+1] + acc[i][2]*als[c0+2] + acc[i][3]*als[c0+3];
        float pr = acc[i][0]*ars[c0] + acc[i][1]*ars[c0+1] + acc[i][2]*ars[c0+2] + acc[i][3]*ars[c0+3];
        #pragma unroll
        for (int o = 8; o; o >>= 1) {
            pl += __shfl_xor_sync(0xffffffffu, pl, o);
            pr += __shfl_xor_sync(0xffffffffu, pr, o);
        }
        if ((l & 15) == 0 && node >= 0) {
            el[node*NH + head] = pl;
            er[node*NH + head] = pr;
        }
    }
}

// ---------------- k_edge: warp per matched edge; exp-weighted red.v4 -----------
__global__ void __launch_bounds__(256) k_edge(int user) {
    const int2* me  = user ? g_medge_u : g_medge_s;
    int cnt         = g_cnt[user ? 2 : 3];
    const float* h  = user ? g_h_u  : g_h_s;
    const float* el = user ? g_el_u : g_el_s;
    const float* er = user ? g_er_u : g_er_s;
    float* acc      = user ? g_acc_u : g_acc_s;
    float* den      = user ? g_den_u : g_den_s;

    int gw = (blockIdx.x*blockDim.x + threadIdx.x) >> 5;
    int nw = (gridDim.x*blockDim.x) >> 5;
    int l  = threadIdx.x & 31;
    int head = l >> 4;

    for (int e = gw; e < cnt; e += nw) {
        int2 sd = me[e];
        float ev = el[sd.x*NH + head] + er[sd.y*NH + head];
        ev = ev > 0.f ? ev : 0.2f * ev;             // leaky_relu(0.2)
        float ex = __expf(ev);                      // softmax w/o max-shift (exact ratio)
        float4 hv = *(const float4*)&h[sd.x*HD + l*4];
        red4(&acc[sd.y*HD + l*4], ex*hv.x, ex*hv.y, ex*hv.z, ex*hv.w);
        if ((l & 15) == 0) atomicAdd(&den[sd.y*NH + head], ex);
    }
}

// ---------------- k_gatfin: /den + bias, LN, ELU, head-mean, +emb, build x -----
__device__ __forceinline__ float blockSum128(float v, float* sred) {
    #pragma unroll
    for (int o = 16; o; o >>= 1) v += __shfl_xor_sync(0xffffffffu, v, o);
    __syncthreads();
    if ((threadIdx.x & 31) == 0) sred[threadIdx.x >> 5] = v;
    __syncthreads();
    return sred[0] + sred[1] + sred[2] + sred[3];
}

__global__ void __launch_bounds__(128) k_gatfin(
        const int* __restrict__ uidx, const int* __restrict__ sidx,
        const float* __restrict__ uemb, const float* __restrict__ semb,
        const float* __restrict__ ubias, const float* __restrict__ ulng, const float* __restrict__ ulnb,
        const float* __restrict__ sbias, const float* __restrict__ slng, const float* __restrict__ slnb) {
    __shared__ float sred[4];
    __shared__ float srow[HD];
    int b = blockIdx.x, t = threadIdx.x;
    int u = uidx[b], s = sidx[b];
    float xu = 0.f, xs = 0.f;

    { // user side
        float v = g_acc_u[u*HD + t] / g_den_u[u*NH + (t >> 6)] + ubias[t];
        float mean = blockSum128(v, sred) * (1.f/HD);
        float d = v - mean;
        float var = blockSum128(d*d, sred) * (1.f/HD);
        float nv = d * rsqrtf(var + 1e-5f) * ulng[t] + ulnb[t];
        nv = nv > 0.f ? nv : expm1f(nv);            // ELU
        __syncthreads();
        srow[t] = nv;
        __syncthreads();
        if (t < DIMK) xu = 0.5f*(srow[t] + srow[t+DIMK]) + uemb[u*DIMK + t];
    }
    { // service side
        float v = g_acc_s[s*HD + t] / g_den_s[s*NH + (t >> 6)] + sbias[t];
        float mean = blockSum128(v, sred) * (1.f/HD);
        float d = v - mean;
        float var = blockSum128(d*d, sred) * (1.f/HD);
        float nv = d * rsqrtf(var + 1e-5f) * slng[t] + slnb[t];
        nv = nv > 0.f ? nv : expm1f(nv);
        __syncthreads();
        srow[t] = nv;
        __syncthreads();
        if (t < DIMK) xs = 0.5f*(srow[t] + srow[t+DIMK]) + semb[s*DIMK + t];
    }
    if (t < DIMK) {
        g_x[b*HD + t]        = xu;
        g_x[b*HD + DIMK + t] = xs;
    }
}

// ---------------- k_mlp: fused 128->128->128->1 with LN/relu, sigmoid ----------
__global__ void __launch_bounds__(256) k_mlp(
        const float* __restrict__ W1, const float* __restrict__ b1,
        const float* __restrict__ g1, const float* __restrict__ bb1,
        const float* __restrict__ W2, const float* __restrict__ b2,
        const float* __restrict__ g2, const float* __restrict__ bb2,
        const float* __restrict__ W3, const float* __restrict__ b3,
        float* __restrict__ out) {
    __shared__ float xs[32][HD];       // 16 KB
    __shared__ float Wch[32*HD];       // 16 KB
    int tid = threadIdx.x;
    int rbase = blockIdx.x * 32;
    int w = tid >> 5, l = tid & 31;
    int r0 = w * 4, c0 = l * 4;

    for (int i = tid; i < 32*HD; i += 256) ((float*)xs)[i] = g_x[rbase*HD + i];

    const float* Wp[2]  = {W1, W2};
    const float* bp[2]  = {b1, b2};
    const float* gp[2]  = {g1, g2};
    const float* bbp[2] = {bb1, bb2};
    float val[4][4];

    for (int layer = 0; layer < 2; layer++) {
        float acc[4][4] = {};
        for (int kc = 0; kc < 4; kc++) {
            __syncthreads();
            for (int i = tid; i < 32*HD; i += 256) Wch[i] = Wp[layer][kc*32*HD + i];
            __syncthreads();
            #pragma unroll
            for (int k4 = 0; k4 < 32; k4 += 4) {
                float4 A0 = *(const float4*)&xs[r0+0][kc*32 + k4];
                float4 A1 = *(const float4*)&xs[r0+1][kc*32 + k4];
                float4 A2 = *(const float4*)&xs[r0+2][kc*32 + k4];
                float4 A3 = *(const float4*)&xs[r0+3][kc*32 + k4];
                #pragma unroll
                for (int kk = 0; kk < 4; kk++) {
                    float4 wv = *(const float4*)&Wch[(k4+kk)*HD + c0];
                    float e0 = FCMP(A0,kk), e1 = FCMP(A1,kk), e2 = FCMP(A2,kk), e3 = FCMP(A3,kk);
                    acc[0][0] += e0*wv.x; acc[0][1] += e0*wv.y; acc[0][2] += e0*wv.z; acc[0][3] += e0*wv.w;
                    acc[1][0] += e1*wv.x; acc[1][1] += e1*wv.y; acc[1][2] += e1*wv.z; acc[1][3] += e1*wv.w;
                    acc[2][0] += e2*wv.x; acc[2][1] += e2*wv.y; acc[2][2] += e2*wv.z; acc[2][3] += e2*wv.w;
                    acc[3][0] += e3*wv.x; acc[3][1] += e3*wv.y; acc[3][2] += e3*wv.z; acc[3][3] += e3*wv.w;
                }
            }
        }
        __syncthreads();   // all GEMM reads of xs complete before overwrite

        float4 bv  = *(const float4*)&bp[layer][c0];
        float4 gv  = *(const float4*)&gp[layer][c0];
        float4 bbv = *(const float4*)&bbp[layer][c0];
        #pragma unroll
        for (int i = 0; i < 4; i++) {
            float a0 = acc[i][0] + bv.x, a1 = acc[i][1] + bv.y;
            float a2 = acc[i][2] + bv.z, a3 = acc[i][3] + bv.w;
            float sum = a0 + a1 + a2 + a3;
            #pragma unroll
            for (int o = 16; o; o >>= 1) sum += __shfl_xor_sync(0xffffffffu, sum, o);
            float mean = sum * (1.f/HD);
            float d0 = a0-mean, d1 = a1-mean, d2 = a2-mean, d3 = a3-mean;
            float sq = d0*d0 + d1*d1 + d2*d2 + d3*d3;
            #pragma unroll
            for (int o = 16; o; o >>= 1) sq += __shfl_xor_sync(0xffffffffu, sq, o);
            float rstd = rsqrtf(sq * (1.f/HD) + 1e-5f);
            float v0 = fmaxf(d0*rstd*gv.x + bbv.x, 0.f);
            float v1 = fmaxf(d1*rstd*gv.y + bbv.y, 0.f);
            float v2 = fmaxf(d2*rstd*gv.z + bbv.z, 0.f);
            float v3 = fmaxf(d3*rstd*gv.w + bbv.w, 0.f);
            xs[r0+i][c0+0] = v0; xs[r0+i][c0+1] = v1;
            xs[r0+i][c0+2] = v2; xs[r0+i][c0+3] = v3;
            val[i][0] = v0; val[i][1] = v1; val[i][2] = v2; val[i][3] = v3;
        }
    }

    float4 w3 = *(const float4*)&W3[c0];
    float bias3 = b3[0];
    #pragma unroll
    for (int i = 0; i < 4; i++) {
        float p = val[i][0]*w3.x + val[i][1]*w3.y + val[i][2]*w3.z + val[i][3]*w3.w;
        #pragma unroll
        for (int o = 16; o; o >>= 1) p += __shfl_xor_sync(0xffffffffu, p, o);
        if (l == 0) out[rbase + r0 + i] = 1.f / (1.f + __expf(-(p + bias3)));
    }
}

// ---------------- launch --------------------------------------------------------
extern "C" void kernel_launch(void* const* d_in, const int* in_sizes, int n_in,
                              void* d_out, int out_size) {
    const int*   uidx  = (const int*)  d_in[0];
    const int*   sidx  = (const int*)  d_in[1];
    const int*   usrc  = (const int*)  d_in[2];
    const int*   udst  = (const int*)  d_in[3];
    const int*   ssrc  = (const int*)  d_in[4];
    const int*   sdst  = (const int*)  d_in[5];
    const float* uemb  = (const float*)d_in[6];
    const float* semb  = (const float*)d_in[7];
    const float* uW    = (const float*)d_in[8];
    const float* ual   = (const float*)d_in[9];
    const float* uar   = (const float*)d_in[10];
    const float* ubias = (const float*)d_in[11];
    const float* ulng  = (const float*)d_in[12];
    const float* ulnb  = (const float*)d_in[13];
    const float* sW    = (const float*)d_in[14];
    const float* sal   = (const float*)d_in[15];
    const float* sar   = (const float*)d_in[16];
    const float* sbias = (const float*)d_in[17];
    const float* slng  = (const float*)d_in[18];
    const float* slnb  = (const float*)d_in[19];
    const float* W1    = (const float*)d_in[20];
    const float* b1    = (const float*)d_in[21];
    const float* g1    = (const float*)d_in[22];
    const float* bb1   = (const float*)d_in[23];
    const float* W2    = (const float*)d_in[24];
    const float* b2    = (const float*)d_in[25];
    const float* g2    = (const float*)d_in[26];
    const float* bb2   = (const float*)d_in[27];
    const float* W3    = (const float*)d_in[28];
    const float* b3    = (const float*)d_in[29];
    float* out = (float*)d_out;

    int B  = in_sizes[0];
    int Eu = in_sizes[2];
    int Es = in_sizes[4];

    k_zero<<<784, 256>>>();
    k_mark<<<B, 128>>>(uidx, sidx);
    k_compact<<<2048, 256>>>(usrc, udst, Eu, 1);
    k_compact<<<2048, 256>>>(ssrc, sdst, Es, 0);
    k_h<<<(NU+31)/32, 256>>>(uemb, uW, ual, uar, 1);
    k_h<<<(NS+31)/32, 256>>>(semb, sW, sal, sar, 0);
    k_edge<<<1184, 256>>>(1);
    k_edge<<<1184, 256>>>(0);
    k_gatfin<<<B, 128>>>(uidx, sidx, uemb, semb, ubias, ulng, ulnb, sbias, slng, slnb);
    k_mlp<<<B/32, 256>>>(W1, b1, g1, bb1, W2, b2, g2, bb2, W3, b3, out);
}

// round 3
// speedup vs baseline: 1.0838x; 1.0838x over previous
#include <cuda_runtime.h>
#include <math.h>

#define NU 100000
#define NS 200000
#define DIMK 64
#define NH 2
#define HD 128          // NH * DIMK
#define EU (NU*9)
#define ESZ (NS*9)
#define BMAX 16384

// ---------------- scratch (static device globals; zero-init at module load) ----
__device__ float g_h_u[NU*HD];
__device__ float g_h_s[NS*HD];
__device__ float g_acc_u[NU*HD];
__device__ float g_acc_s[NS*HD];
__device__ float g_den_u[NU*NH];
__device__ float g_den_s[NS*NH];
__device__ float g_el_u[NU*NH];
__device__ float g_er_u[NU*NH];
__device__ float g_el_s[NS*NH];
__device__ float g_er_s[NS*NH];
__device__ int   g_need_u[NU];
__device__ int   g_need_s[NS];
__device__ int   g_sflag_u[NU];
__device__ int   g_sflag_s[NS];
__device__ int   g_slist_u[NU];
__device__ int   g_slist_s[NS];
__device__ int2  g_medge_u[EU];
__device__ int2  g_medge_s[ESZ];
__device__ int   g_cnt[4];   // [0]=nsrc_u [1]=nsrc_s [2]=nedge_u [3]=nedge_s
__device__ float g_x[BMAX*HD];

// ---------------- helpers ------------------------------------------------------
__device__ __forceinline__ void red4(float* p, float a, float b, float c, float d) {
    asm volatile("{ .reg .u64 q; cvta.to.global.u64 q, %0;"
                 "  red.global.add.v4.f32 [q], {%1, %2, %3, %4}; }"
                 :: "l"(p), "f"(a), "f"(b), "f"(c), "f"(d) : "memory");
}

#define FCMP(v,kk) ((kk)==0?(v).x:((kk)==1?(v).y:((kk)==2?(v).z:(v).w)))

// ---------------- k_zero: reset flags + counters -------------------------------
__global__ void k_zero() {
    int i = blockIdx.x*blockDim.x + threadIdx.x;
    int st = gridDim.x*blockDim.x;
    for (int j = i; j < NU; j += st) { g_need_u[j] = 0; g_sflag_u[j] = 0; }
    for (int j = i; j < NS; j += st) { g_need_s[j] = 0; g_sflag_s[j] = 0; }
    if (i < 4) g_cnt[i] = 0;
}

// ---------------- k_mark: mark needed dsts, zero their acc/den rows ------------
__global__ void __launch_bounds__(128) k_mark(const int* __restrict__ uidx,
                                              const int* __restrict__ sidx) {
    int b = blockIdx.x, t = threadIdx.x;
    int u = uidx[b], s = sidx[b];
    g_acc_u[u*HD + t] = 0.f;
    g_acc_s[s*HD + t] = 0.f;
    if (t < NH) { g_den_u[u*NH + t] = 0.f; g_den_s[s*NH + t] = 0.f; }
    if (t == 0) { g_need_u[u] = 1; g_need_s[s] = 1; }
}

// ---------------- k_compact: filter edges by needed dst; dedupe srcs -----------
// 4 edges/thread (int4 dst loads) + warp-aggregated slot allocation: one
// atomicAdd(cntE) per warp instead of one per matched edge.
__global__ void __launch_bounds__(256) k_compact(const int* __restrict__ src,
                                                 const int* __restrict__ dst,
                                                 int E, int user) {
    const int* __restrict__ need = user ? g_need_u  : g_need_s;
    int*  sflag     = user ? g_sflag_u : g_sflag_s;
    int*  slist     = user ? g_slist_u : g_slist_s;
    int2* medge     = user ? g_medge_u : g_medge_s;
    int*  cntS      = &g_cnt[user ? 0 : 1];
    int*  cntE      = &g_cnt[user ? 2 : 3];

    int tid = blockIdx.x*blockDim.x + threadIdx.x;
    int l   = threadIdx.x & 31;
    long long stride = (long long)gridDim.x * blockDim.x * 4;

    for (long long i0 = (long long)tid * 4; i0 < E; i0 += stride) {
        int d0=-1, d1=-1, d2=-1, d3=-1;
        if (i0 + 3 < E) {
            int4 dv = *(const int4*)(dst + i0);
            d0 = dv.x; d1 = dv.y; d2 = dv.z; d3 = dv.w;
        } else {
            if (i0     < E) d0 = dst[i0];
            if (i0 + 1 < E) d1 = dst[i0+1];
            if (i0 + 2 < E) d2 = dst[i0+2];
            if (i0 + 3 < E) d3 = dst[i0+3];
        }
        bool m0 = (d0 >= 0) && __ldg(&need[d0]);
        bool m1 = (d1 >= 0) && __ldg(&need[d1]);
        bool m2 = (d2 >= 0) && __ldg(&need[d2]);
        bool m3 = (d3 >= 0) && __ldg(&need[d3]);
        int mloc = (int)m0 + (int)m1 + (int)m2 + (int)m3;

        // warp inclusive scan of mloc
        int pre = mloc;
        #pragma unroll
        for (int o = 1; o < 32; o <<= 1) {
            int v = __shfl_up_sync(0xffffffffu, pre, o);
            if (l >= o) pre += v;
        }
        int total = __shfl_sync(0xffffffffu, pre, 31);
        int base = 0;
        if (total > 0) {
            if (l == 31) base = atomicAdd(cntE, total);
            base = __shfl_sync(0xffffffffu, base, 31);
        }
        int off = base + pre - mloc;

        if (mloc > 0) {
            #pragma unroll
            for (int j = 0; j < 4; j++) {
                bool m = (j==0) ? m0 : (j==1) ? m1 : (j==2) ? m2 : m3;
                int  d = (j==0) ? d0 : (j==1) ? d1 : (j==2) ? d2 : d3;
                if (m) {
                    int s = src[i0 + j];
                    medge[off++] = make_int2(s, d);
                    if (atomicExch(&sflag[s], 1) == 0)
                        slist[atomicAdd(cntS, 1)] = s;
                }
            }
        }
    }
}

// ---------------- k_h: h = emb@W (register-tiled), plus el/er, for flagged srcs
__global__ void __launch_bounds__(256,4) k_h(const float* __restrict__ emb,
                                             const float* __restrict__ W,
                                             const float* __restrict__ al_,
                                             const float* __restrict__ ar_,
                                             int user) {
    float* h  = user ? g_h_u  : g_h_s;
    float* el = user ? g_el_u : g_el_s;
    float* er = user ? g_er_u : g_er_s;
    const int* slist = user ? g_slist_u : g_slist_s;
    int nsrc = g_cnt[user ? 0 : 1];

    __shared__ float Ws[DIMK*HD];      // 32 KB
    __shared__ float Es[32][DIMK];     // 8 KB
    __shared__ float als[HD], ars[HD];
    __shared__ int   rows[32];

    int tile0 = blockIdx.x * 32;
    if (tile0 >= nsrc) return;
    int tid = threadIdx.x;

    for (int i = tid; i < DIMK*HD; i += 256) Ws[i] = W[i];
    if (tid < HD) { als[tid] = al_[tid]; ars[tid] = ar_[tid]; }
    if (tid < 32) rows[tid] = (tile0 + tid < nsrc) ? slist[tile0 + tid] : -1;
    __syncthreads();
    for (int idx = tid; idx < 32*DIMK; idx += 256) {
        int r = idx >> 6, k = idx & 63;
        int node = rows[r];
        Es[r][k] = (node >= 0) ? emb[node*DIMK + k] : 0.f;
    }
    __syncthreads();

    int w = tid >> 5, l = tid & 31;
    int r0 = w * 4, c0 = l * 4;
    float acc[4][4] = {};

    for (int k4 = 0; k4 < DIMK; k4 += 4) {
        float4 A0 = *(const float4*)&Es[r0+0][k4];
        float4 A1 = *(const float4*)&Es[r0+1][k4];
        float4 A2 = *(const float4*)&Es[r0+2][k4];
        float4 A3 = *(const float4*)&Es[r0+3][k4];
        #pragma unroll
        for (int kk = 0; kk < 4; kk++) {
            float4 wv = *(const float4*)&Ws[(k4+kk)*HD + c0];
            float e0 = FCMP(A0,kk), e1 = FCMP(A1,kk), e2 = FCMP(A2,kk), e3 = FCMP(A3,kk);
            acc[0][0] += e0*wv.x; acc[0][1] += e0*wv.y; acc[0][2] += e0*wv.z; acc[0][3] += e0*wv.w;
            acc[1][0] += e1*wv.x; acc[1][1] += e1*wv.y; acc[1][2] += e1*wv.z; acc[1][3] += e1*wv.w;
            acc[2][0] += e2*wv.x; acc[2][1] += e2*wv.y; acc[2][2] += e2*wv.z; acc[2][3] += e2*wv.w;
            acc[3][0] += e3*wv.x; acc[3][1] += e3*wv.y; acc[3][2] += e3*wv.z; acc[3][3] += e3*wv.w;
        }
    }

    int head = l >> 4;   // lanes 0-15 head0, 16-31 head1 (c0 = l*4)
    #pragma unroll
    for (int i = 0; i < 4; i++) {
        int node = rows[r0+i];
        if (node >= 0)
            *(float4*)&h[node*HD + c0] = make_float4(acc[i][0], acc[i][1], acc[i][2], acc[i][3]);
        float pl = acc[i][0]*als[c0] + acc[i][1]*als[c0+1] + acc[i][2]*als[c0+2] + acc[i][3]*als[c0+3];
        float pr = acc[i][0]*ars[c0] + acc[i][1]*ars[c0+1] + acc[i][2]*ars[c0+2] + acc[i][3]*ars[c0+3];
        #pragma unroll
        for (int o = 8; o; o >>= 1) {
            pl += __shfl_xor_sync(0xffffffffu, pl, o);
            pr += __shfl_xor_sync(0xffffffffu, pr, o);
        }
        if ((l & 15) == 0 && node >= 0) {
            el[node*NH + head] = pl;
            er[node*NH + head] = pr;
        }
    }
}

// ---------------- k_edge: warp per matched edge; exp-weighted red.v4 -----------
__global__ void __launch_bounds__(256) k_edge(int user) {
    const int2* me  = user ? g_medge_u : g_medge_s;
    int cnt         = g_cnt[user ? 2 : 3];
    const float* h  = user ? g_h_u  : g_h_s;
    const float* el = user ? g_el_u : g_el_s;
    const float* er = user ? g_er_u : g_er_s;
    float* acc      = user ? g_acc_u : g_acc_s;
    float* den      = user ? g_den_u : g_den_s;

    int gw = (blockIdx.x*blockDim.x + threadIdx.x) >> 5;
    int nw = (gridDim.x*blockDim.x) >> 5;
    int l  = threadIdx.x & 31;
    int head = l >> 4;

    for (int e = gw; e < cnt; e += nw) {
        int2 sd = me[e];
        float ev = el[sd.x*NH + head] + er[sd.y*NH + head];
        ev = ev > 0.f ? ev : 0.2f * ev;             // leaky_relu(0.2)
        float ex = __expf(ev);                      // softmax w/o max-shift (exact ratio)
        float4 hv = *(const float4*)&h[sd.x*HD + l*4];
        red4(&acc[sd.y*HD + l*4], ex*hv.x, ex*hv.y, ex*hv.z, ex*hv.w);
        if ((l & 15) == 0) atomicAdd(&den[sd.y*NH + head], ex);
    }
}

// ---------------- k_gatfin: /den + bias, LN, ELU, head-mean, +emb, build x -----
__device__ __forceinline__ float blockSum128(float v, float* sred) {
    #pragma unroll
    for (int o = 16; o; o >>= 1) v += __shfl_xor_sync(0xffffffffu, v, o);
    __syncthreads();
    if ((threadIdx.x & 31) == 0) sred[threadIdx.x >> 5] = v;
    __syncthreads();
    return sred[0] + sred[1] + sred[2] + sred[3];
}

__global__ void __launch_bounds__(128) k_gatfin(
        const int* __restrict__ uidx, const int* __restrict__ sidx,
        const float* __restrict__ uemb, const float* __restrict__ semb,
        const float* __restrict__ ubias, const float* __restrict__ ulng, const float* __restrict__ ulnb,
        const float* __restrict__ sbias, const float* __restrict__ slng, const float* __restrict__ slnb) {
    __shared__ float sred[4];
    __shared__ float srow[HD];
    int b = blockIdx.x, t = threadIdx.x;
    int u = uidx[b], s = sidx[b];
    float xu = 0.f, xs = 0.f;

    { // user side
        float v = g_acc_u[u*HD + t] / g_den_u[u*NH + (t >> 6)] + ubias[t];
        float mean = blockSum128(v, sred) * (1.f/HD);
        float d = v - mean;
        float var = blockSum128(d*d, sred) * (1.f/HD);
        float nv = d * rsqrtf(var + 1e-5f) * ulng[t] + ulnb[t];
        nv = nv > 0.f ? nv : expm1f(nv);            // ELU
        __syncthreads();
        srow[t] = nv;
        __syncthreads();
        if (t < DIMK) xu = 0.5f*(srow[t] + srow[t+DIMK]) + uemb[u*DIMK + t];
    }
    { // service side
        float v = g_acc_s[s*HD + t] / g_den_s[s*NH + (t >> 6)] + sbias[t];
        float mean = blockSum128(v, sred) * (1.f/HD);
        float d = v - mean;
        float var = blockSum128(d*d, sred) * (1.f/HD);
        float nv = d * rsqrtf(var + 1e-5f) * slng[t] + slnb[t];
        nv = nv > 0.f ? nv : expm1f(nv);
        __syncthreads();
        srow[t] = nv;
        __syncthreads();
        if (t < DIMK) xs = 0.5f*(srow[t] + srow[t+DIMK]) + semb[s*DIMK + t];
    }
    if (t < DIMK) {
        g_x[b*HD + t]        = xu;
        g_x[b*HD + DIMK + t] = xs;
    }
}

// ---------------- k_mlp: fused 128->128->128->1 with LN/relu, sigmoid ----------
__global__ void __launch_bounds__(256) k_mlp(
        const float* __restrict__ W1, const float* __restrict__ b1,
        const float* __restrict__ g1, const float* __restrict__ bb1,
        const float* __restrict__ W2, const float* __restrict__ b2,
        const float* __restrict__ g2, const float* __restrict__ bb2,
        const float* __restrict__ W3, const float* __restrict__ b3,
        float* __restrict__ out) {
    __shared__ float xs[32][HD];       // 16 KB
    __shared__ float Wch[32*HD];       // 16 KB
    int tid = threadIdx.x;
    int rbase = blockIdx.x * 32;
    int w = tid >> 5, l = tid & 31;
    int r0 = w * 4, c0 = l * 4;

    for (int i = tid; i < 32*HD; i += 256) ((float*)xs)[i] = g_x[rbase*HD + i];

    const float* Wp[2]  = {W1, W2};
    const float* bp[2]  = {b1, b2};
    const float* gp[2]  = {g1, g2};
    const float* bbp[2] = {bb1, bb2};
    float val[4][4];

    for (int layer = 0; layer < 2; layer++) {
        float acc[4][4] = {};
        for (int kc = 0; kc < 4; kc++) {
            __syncthreads();
            for (int i = tid; i < 32*HD; i += 256) Wch[i] = Wp[layer][kc*32*HD + i];
            __syncthreads();
            #pragma unroll
            for (int k4 = 0; k4 < 32; k4 += 4) {
                float4 A0 = *(const float4*)&xs[r0+0][kc*32 + k4];
                float4 A1 = *(const float4*)&xs[r0+1][kc*32 + k4];
                float4 A2 = *(const float4*)&xs[r0+2][kc*32 + k4];
                float4 A3 = *(const float4*)&xs[r0+3][kc*32 + k4];
                #pragma unroll
                for (int kk = 0; kk < 4; kk++) {
                    float4 wv = *(const float4*)&Wch[(k4+kk)*HD + c0];
                    float e0 = FCMP(A0,kk), e1 = FCMP(A1,kk), e2 = FCMP(A2,kk), e3 = FCMP(A3,kk);
                    acc[0][0] += e0*wv.x; acc[0][1] += e0*wv.y; acc[0][2] += e0*wv.z; acc[0][3] += e0*wv.w;
                    acc[1][0] += e1*wv.x; acc[1][1] += e1*wv.y; acc[1][2] += e1*wv.z; acc[1][3] += e1*wv.w;
                    acc[2][0] += e2*wv.x; acc[2][1] += e2*wv.y; acc[2][2] += e2*wv.z; acc[2][3] += e2*wv.w;
                    acc[3][0] += e3*wv.x; acc[3][1] += e3*wv.y; acc[3][2] += e3*wv.z; acc[3][3] += e3*wv.w;
                }
            }
        }
        __syncthreads();   // all GEMM reads of xs complete before overwrite

        float4 bv  = *(const float4*)&bp[layer][c0];
        float4 gv  = *(const float4*)&gp[layer][c0];
        float4 bbv = *(const float4*)&bbp[layer][c0];
        #pragma unroll
        for (int i = 0; i < 4; i++) {
            float a0 = acc[i][0] + bv.x, a1 = acc[i][1] + bv.y;
            float a2 = acc[i][2] + bv.z, a3 = acc[i][3] + bv.w;
            float sum = a0 + a1 + a2 + a3;
            #pragma unroll
            for (int o = 16; o; o >>= 1) sum += __shfl_xor_sync(0xffffffffu, sum, o);
            float mean = sum * (1.f/HD);
            float d0 = a0-mean, d1 = a1-mean, d2 = a2-mean, d3 = a3-mean;
            float sq = d0*d0 + d1*d1 + d2*d2 + d3*d3;
            #pragma unroll
            for (int o = 16; o; o >>= 1) sq += __shfl_xor_sync(0xffffffffu, sq, o);
            float rstd = rsqrtf(sq * (1.f/HD) + 1e-5f);
            float v0 = fmaxf(d0*rstd*gv.x + bbv.x, 0.f);
            float v1 = fmaxf(d1*rstd*gv.y + bbv.y, 0.f);
            float v2 = fmaxf(d2*rstd*gv.z + bbv.z, 0.f);
            float v3 = fmaxf(d3*rstd*gv.w + bbv.w, 0.f);
            xs[r0+i][c0+0] = v0; xs[r0+i][c0+1] = v1;
            xs[r0+i][c0+2] = v2; xs[r0+i][c0+3] = v3;
            val[i][0] = v0; val[i][1] = v1; val[i][2] = v2; val[i][3] = v3;
        }
    }

    float4 w3 = *(const float4*)&W3[c0];
    float bias3 = b3[0];
    #pragma unroll
    for (int i = 0; i < 4; i++) {
        float p = val[i][0]*w3.x + val[i][1]*w3.y + val[i][2]*w3.z + val[i][3]*w3.w;
        #pragma unroll
        for (int o = 16; o; o >>= 1) p += __shfl_xor_sync(0xffffffffu, p, o);
        if (l == 0) out[rbase + r0 + i] = 1.f / (1.f + __expf(-(p + bias3)));
    }
}

// ---------------- launch --------------------------------------------------------
extern "C" void kernel_launch(void* const* d_in, const int* in_sizes, int n_in,
                              void* d_out, int out_size) {
    const int*   uidx  = (const int*)  d_in[0];
    const int*   sidx  = (const int*)  d_in[1];
    const int*   usrc  = (const int*)  d_in[2];
    const int*   udst  = (const int*)  d_in[3];
    const int*   ssrc  = (const int*)  d_in[4];
    const int*   sdst  = (const int*)  d_in[5];
    const float* uemb  = (const float*)d_in[6];
    const float* semb  = (const float*)d_in[7];
    const float* uW    = (const float*)d_in[8];
    const float* ual   = (const float*)d_in[9];
    const float* uar   = (const float*)d_in[10];
    const float* ubias = (const float*)d_in[11];
    const float* ulng  = (const float*)d_in[12];
    const float* ulnb  = (const float*)d_in[13];
    const float* sW    = (const float*)d_in[14];
    const float* sal   = (const float*)d_in[15];
    const float* sar   = (const float*)d_in[16];
    const float* sbias = (const float*)d_in[17];
    const float* slng  = (const float*)d_in[18];
    const float* slnb  = (const float*)d_in[19];
    const float* W1    = (const float*)d_in[20];
    const float* b1    = (const float*)d_in[21];
    const float* g1    = (const float*)d_in[22];
    const float* bb1   = (const float*)d_in[23];
    const float* W2    = (const float*)d_in[24];
    const float* b2    = (const float*)d_in[25];
    const float* g2    = (const float*)d_in[26];
    const float* bb2   = (const float*)d_in[27];
    const float* W3    = (const float*)d_in[28];
    const float* b3    = (const float*)d_in[29];
    float* out = (float*)d_out;

    int B  = in_sizes[0];
    int Eu = in_sizes[2];
    int Es = in_sizes[4];

    k_zero<<<784, 256>>>();
    k_mark<<<B, 128>>>(uidx, sidx);
    {
        int gu = min(2048, (Eu/4 + 255) / 256);
        int gs = min(2048, (Es/4 + 255) / 256);
        k_compact<<<gu, 256>>>(usrc, udst, Eu, 1);
        k_compact<<<gs, 256>>>(ssrc, sdst, Es, 0);
    }
    k_h<<<(NU+31)/32, 256>>>(uemb, uW, ual, uar, 1);
    k_h<<<(NS+31)/32, 256>>>(semb, sW, sal, sar, 0);
    k_edge<<<1184, 256>>>(1);
    k_edge<<<1184, 256>>>(0);
    k_gatfin<<<B, 128>>>(uidx, sidx, uemb, semb, ubias, ulng, ulnb, sbias, slng, slnb);
    k_mlp<<<B/32, 256>>>(W1, b1, g1, bb1, W2, b2, g2, bb2, W3, b3, out);
}